// round 1
// baseline (speedup 1.0000x reference)
#include <cuda_runtime.h>
#include <math.h>

#define NN 100000
#define EE 600000
#define HH 128
#define LL 3
#define BB 16
#define NF 12
#define EF 3
#define BN_EPS 1e-5f
#define LN_EPS 1e-5f

// ---------------- scratch (static device globals; no runtime alloc) ----------
__device__ float g_hcat[(size_t)NN * 4 * HH];   // h0..h3 concatenated per node
__device__ float g_agg [(size_t)NN * HH];       // agg / pre-LN buffer (reused)
__device__ float g_z1  [(size_t)NN * 2 * HH];   // mlp hidden / out1 result
__device__ float g_gsum[BB * HH];
__device__ float g_cnt [BB];

// ---------------- small kernels ----------------------------------------------
__global__ void k_zero_pool() {
    int i = blockIdx.x * blockDim.x + threadIdx.x;
    if (i < BB * HH) g_gsum[i] = 0.f;
    if (i < BB) g_cnt[i] = 0.f;
}

__global__ void k_input(const float* __restrict__ x, const float* __restrict__ W,
                        const float* __restrict__ b) {
    int idx = blockIdx.x * blockDim.x + threadIdx.x;
    if (idx >= NN * HH) return;
    int n = idx >> 7, j = idx & 127;
    const float* xr = x + (size_t)n * NF;
    float acc = b[j];
#pragma unroll
    for (int f = 0; f < NF; f++) acc += xr[f] * W[f * HH + j];
    g_hcat[(size_t)n * 512 + j] = acc;
}

__global__ void k_scale(const float* __restrict__ eps, int layer) {
    int idx = blockIdx.x * blockDim.x + threadIdx.x;
    if (idx >= NN * HH) return;
    int n = idx >> 7, j = idx & 127;
    g_agg[idx] = (1.f + eps[layer]) * g_hcat[(size_t)n * 512 + layer * HH + j];
}

// one warp per edge: fused edge-proj + gather(h[src]) + atomic scatter to agg[dst]
__global__ void k_edge(const int* __restrict__ ei, const float* __restrict__ ea,
                       const float* __restrict__ eW, const float* __restrict__ eb,
                       int layer) {
    int warp = (blockIdx.x * blockDim.x + threadIdx.x) >> 5;
    int lane = threadIdx.x & 31;
    if (warp >= EE) return;
    int src = ei[warp];
    int dst = ei[EE + warp];
    float a0 = ea[warp * 3 + 0], a1 = ea[warp * 3 + 1], a2 = ea[warp * 3 + 2];
    const float* W = eW + layer * EF * HH;
    const float* bb = eb + layer * HH;
    int j = lane * 4;
    float4 hv = *(const float4*)(g_hcat + (size_t)src * 512 + layer * HH + j);
    float4 w0 = *(const float4*)(W + 0 * HH + j);
    float4 w1 = *(const float4*)(W + 1 * HH + j);
    float4 w2 = *(const float4*)(W + 2 * HH + j);
    float4 bv = *(const float4*)(bb + j);
    float c0 = hv.x + bv.x + a0 * w0.x + a1 * w1.x + a2 * w2.x;
    float c1 = hv.y + bv.y + a0 * w0.y + a1 * w1.y + a2 * w2.y;
    float c2 = hv.z + bv.z + a0 * w0.z + a1 * w1.z + a2 * w2.z;
    float c3 = hv.w + bv.w + a0 * w0.w + a1 * w1.w + a2 * w2.w;
    float* out = g_agg + (size_t)dst * HH + j;
    atomicAdd(out + 0, c0);
    atomicAdd(out + 1, c1);
    atomicAdd(out + 2, c2);
    atomicAdd(out + 3, c3);
}

// ---------------- tiled GEMM with fused epilogues -----------------------------
// EPI 0: bn+relu        (mlp1)  -> out stride NC
// EPI 1: bn+relu + h    (mlp2)  -> out stride NC (pre-LN)
// EPI 2: relu           (out1)
// EPI 3: none           (out2)
template <int K, int NC, int EPI>
__global__ void k_gemm(const float* __restrict__ A, const float* __restrict__ W,
                       const float* __restrict__ bias,
                       const float* __restrict__ bng, const float* __restrict__ bnb,
                       const float* __restrict__ bnrm, const float* __restrict__ bnrv,
                       const float* __restrict__ hres, float* __restrict__ out) {
    constexpr int TN = NC / 32;
    constexpr int KC = 32;
    __shared__ float As[64 * KC];
    __shared__ float Bs[KC * NC];
    int t = threadIdx.x;
    int tx = t & 31, ty = t >> 5;
    int n0 = blockIdx.x * 64;

    float acc[8][TN];
#pragma unroll
    for (int r = 0; r < 8; r++)
#pragma unroll
        for (int u = 0; u < TN; u++) acc[r][u] = 0.f;

    for (int k0 = 0; k0 < K; k0 += KC) {
        // load A tile (64 x 32), zero-pad OOB rows
#pragma unroll
        for (int i = 0; i < 2; i++) {
            int f = t + i * 256;
            int r = f >> 3, c4 = f & 7;
            int n = n0 + r;
            float4 v = make_float4(0.f, 0.f, 0.f, 0.f);
            if (n < NN) v = *(const float4*)(A + (size_t)n * K + k0 + c4 * 4);
            *(float4*)(As + r * KC + c4 * 4) = v;
        }
        // load B tile (32 x NC)
#pragma unroll
        for (int i = 0; i < (KC * NC) / 1024; i++) {
            int f = t + i * 256;
            int r = f / (NC / 4), c4 = f % (NC / 4);
            *(float4*)(Bs + r * NC + c4 * 4) =
                *(const float4*)(W + (size_t)(k0 + r) * NC + c4 * 4);
        }
        __syncthreads();
#pragma unroll
        for (int kc = 0; kc < KC; kc++) {
            float a[8], bf[TN];
#pragma unroll
            for (int r = 0; r < 8; r++) a[r] = As[(ty * 8 + r) * KC + kc];
#pragma unroll
            for (int u = 0; u < TN; u++) bf[u] = Bs[kc * NC + tx + u * 32];
#pragma unroll
            for (int r = 0; r < 8; r++)
#pragma unroll
                for (int u = 0; u < TN; u++) acc[r][u] += a[r] * bf[u];
        }
        __syncthreads();
    }

    float bsv[TN], sc[TN], sh[TN];
#pragma unroll
    for (int u = 0; u < TN; u++) {
        int j = tx + u * 32;
        bsv[u] = bias[j];
        if (EPI == 0 || EPI == 1) {
            float s = bng[j] * rsqrtf(bnrv[j] + BN_EPS);
            sc[u] = s;
            sh[u] = bnb[j] - bnrm[j] * s;
        }
    }
#pragma unroll
    for (int r = 0; r < 8; r++) {
        int n = n0 + ty * 8 + r;
        if (n >= NN) continue;
#pragma unroll
        for (int u = 0; u < TN; u++) {
            int j = tx + u * 32;
            float v = acc[r][u] + bsv[u];
            if (EPI == 0 || EPI == 1) v = fmaxf(v * sc[u] + sh[u], 0.f);
            if (EPI == 1) v += hres[(size_t)n * 512 + j];
            if (EPI == 2) v = fmaxf(v, 0.f);
            out[(size_t)n * NC + j] = v;
        }
    }
}

// LayerNorm over the pre-LN buffer (g_agg), writes hcat slot layer+1
__global__ void k_ln(const float* __restrict__ lng, const float* __restrict__ lnb,
                     int layer) {
    int node = (blockIdx.x * blockDim.x + threadIdx.x) >> 5;
    if (node >= NN) return;
    int lane = threadIdx.x & 31;
    float4 v = *(const float4*)(g_agg + (size_t)node * HH + lane * 4);
    float s = v.x + v.y + v.z + v.w;
#pragma unroll
    for (int o = 16; o > 0; o >>= 1) s += __shfl_xor_sync(0xffffffffu, s, o);
    float mu = s * (1.f / 128.f);
    float dx = v.x - mu, dy = v.y - mu, dz = v.z - mu, dw = v.w - mu;
    float q = dx * dx + dy * dy + dz * dz + dw * dw;
#pragma unroll
    for (int o = 16; o > 0; o >>= 1) q += __shfl_xor_sync(0xffffffffu, q, o);
    float inv = rsqrtf(q * (1.f / 128.f) + LN_EPS);
    int j = lane * 4;
    float4 g = *(const float4*)(lng + layer * HH + j);
    float4 b = *(const float4*)(lnb + layer * HH + j);
    float4 o4;
    o4.x = dx * inv * g.x + b.x;
    o4.y = dy * inv * g.y + b.y;
    o4.z = dz * inv * g.z + b.z;
    o4.w = dw * inv * g.w + b.w;
    *(float4*)(g_hcat + (size_t)node * 512 + (layer + 1) * HH + j) = o4;
}

// pooled sum with run-length pre-aggregation over sorted batch ids
__global__ void k_pool(const int* __restrict__ batch, const float* __restrict__ emb) {
    int c = blockIdx.x;
    int j = threadIdx.x;
    int n0 = c * 32;
    __shared__ int sb[32];
    if (j < 32) sb[j] = (n0 + j < NN) ? batch[n0 + j] : -1;
    __syncthreads();
    float acc = 0.f;
    int bcur = sb[0];
    for (int m = 0; m < 32; m++) {
        int b = sb[m];
        if (b < 0) break;
        if (b != bcur) {
            atomicAdd(&g_gsum[bcur * HH + j], acc);
            acc = 0.f;
            bcur = b;
        }
        acc += emb[(size_t)(n0 + m) * HH + j];
    }
    if (bcur >= 0) atomicAdd(&g_gsum[bcur * HH + j], acc);
    if (j == 0) {
        float cn = 0.f;
        int bc = sb[0];
        for (int m = 0; m < 32; m++) {
            int b = sb[m];
            if (b < 0) break;
            if (b != bc) { atomicAdd(&g_cnt[bc], cn); cn = 0.f; bc = b; }
            cn += 1.f;
        }
        if (bc >= 0) atomicAdd(&g_cnt[bc], cn);
    }
}

__global__ void k_finish(float* __restrict__ out_graph) {
    int i = blockIdx.x * blockDim.x + threadIdx.x;
    if (i >= BB * HH) return;
    out_graph[i] = g_gsum[i] / fmaxf(g_cnt[i >> 7], 1.f);
}

// ---------------- launcher ----------------------------------------------------
extern "C" void kernel_launch(void* const* d_in, const int* in_sizes, int n_in,
                              void* d_out, int out_size) {
    const float* x      = (const float*)d_in[0];
    const int*   ei     = (const int*)  d_in[1];
    const float* ea     = (const float*)d_in[2];
    const int*   batch  = (const int*)  d_in[3];
    const float* in_W   = (const float*)d_in[4];
    const float* in_b   = (const float*)d_in[5];
    const float* edge_W = (const float*)d_in[6];
    const float* edge_b = (const float*)d_in[7];
    const float* mlp_W1 = (const float*)d_in[8];
    const float* mlp_b1 = (const float*)d_in[9];
    const float* bn1_g  = (const float*)d_in[10];
    const float* bn1_b  = (const float*)d_in[11];
    const float* bn1_rm = (const float*)d_in[12];
    const float* bn1_rv = (const float*)d_in[13];
    const float* mlp_W2 = (const float*)d_in[14];
    const float* mlp_b2 = (const float*)d_in[15];
    const float* bn2_g  = (const float*)d_in[16];
    const float* bn2_b  = (const float*)d_in[17];
    const float* bn2_rm = (const float*)d_in[18];
    const float* bn2_rv = (const float*)d_in[19];
    const float* eps    = (const float*)d_in[20];
    const float* ln_g   = (const float*)d_in[21];
    const float* ln_b   = (const float*)d_in[22];
    const float* out_W1 = (const float*)d_in[23];
    const float* out_b1 = (const float*)d_in[24];
    const float* out_W2 = (const float*)d_in[25];
    const float* out_b2 = (const float*)d_in[26];

    float* node_emb  = (float*)d_out;                       // [N, H]
    float* graph_emb = (float*)d_out + (size_t)NN * HH;     // [B, H]

    float* g_hcat_p; cudaGetSymbolAddress((void**)&g_hcat_p, g_hcat);
    float* g_agg_p;  cudaGetSymbolAddress((void**)&g_agg_p,  g_agg);
    float* g_z1_p;   cudaGetSymbolAddress((void**)&g_z1_p,   g_z1);

    const int NT = 256;
    k_zero_pool<<<(BB * HH + NT - 1) / NT, NT>>>();
    k_input<<<(NN * HH + NT - 1) / NT, NT>>>(x, in_W, in_b);

    const int gemm_grid = (NN + 63) / 64;
    for (int l = 0; l < LL; l++) {
        k_scale<<<(NN * HH + NT - 1) / NT, NT>>>(eps, l);
        k_edge<<<(EE * 32 + NT - 1) / NT, NT>>>(ei, ea, edge_W, edge_b, l);
        // mlp1: agg[N,128] @ W1 -> z1[N,256], bn1+relu
        k_gemm<128, 256, 0><<<gemm_grid, 256>>>(
            g_agg_p, mlp_W1 + (size_t)l * 128 * 256, mlp_b1 + l * 256,
            bn1_g + l * 256, bn1_b + l * 256, bn1_rm + l * 256, bn1_rv + l * 256,
            nullptr, g_z1_p);
        // mlp2: z1[N,256] @ W2 -> preLN[N,128] (bn2+relu + residual h), into g_agg
        k_gemm<256, 128, 1><<<gemm_grid, 256>>>(
            g_z1_p, mlp_W2 + (size_t)l * 256 * 128, mlp_b2 + l * 128,
            bn2_g + l * 128, bn2_b + l * 128, bn2_rm + l * 128, bn2_rv + l * 128,
            g_hcat_p + l * HH, g_agg_p);
        k_ln<<<(NN * 32 + NT - 1) / NT, NT>>>(ln_g, ln_b, l);
    }
    // out1: hcat[N,512] @ W1 -> relu -> g_z1[N,128]
    k_gemm<512, 128, 2><<<gemm_grid, 256>>>(
        g_hcat_p, out_W1, out_b1, nullptr, nullptr, nullptr, nullptr, nullptr, g_z1_p);
    // out2: g_z1[N,128] @ W2 -> node_emb
    k_gemm<128, 128, 3><<<gemm_grid, 256>>>(
        g_z1_p, out_W2, out_b2, nullptr, nullptr, nullptr, nullptr, nullptr, node_emb);

    k_pool<<<(NN + 31) / 32, 128>>>(batch, node_emb);
    k_finish<<<(BB * HH + NT - 1) / NT, NT>>>(graph_emb);
}

// round 2
// speedup vs baseline: 1.7464x; 1.7464x over previous
#include <cuda_runtime.h>
#include <math.h>
#include <stdint.h>

#define NN 100000
#define EE 600000
#define HH 128
#define LL 3
#define BB 16
#define NF 12
#define EF 3
#define BN_EPS 1e-5f
#define LN_EPS 1e-5f

// ---------------- scratch (static device globals; no runtime alloc) ----------
__device__ float g_hcat[(size_t)NN * 4 * HH];   // h0..h3 concatenated per node
__device__ float g_agg [(size_t)NN * HH];       // agg / pre-LN buffer (reused)
__device__ float g_z1  [(size_t)NN * 2 * HH];   // mlp hidden / out1 result
__device__ float g_gsum[BB * HH];
__device__ float g_cnt [BB];

// ---------------- helpers ----------------------------------------------------
__device__ __forceinline__ uint32_t f2tf(float f) {
    uint32_t r;
    asm("cvt.rna.tf32.f32 %0, %1;" : "=r"(r) : "f"(f));
    return r;
}

__device__ __forceinline__ void mma_tf32(float* c, const uint32_t* a, const uint32_t* b) {
    asm volatile(
        "mma.sync.aligned.m16n8k8.row.col.f32.tf32.tf32.f32 "
        "{%0,%1,%2,%3},{%4,%5,%6,%7},{%8,%9},{%0,%1,%2,%3};\n"
        : "+f"(c[0]), "+f"(c[1]), "+f"(c[2]), "+f"(c[3])
        : "r"(a[0]), "r"(a[1]), "r"(a[2]), "r"(a[3]), "r"(b[0]), "r"(b[1]));
}

// ---------------- small kernels ----------------------------------------------
__global__ void k_zero_pool() {
    int i = blockIdx.x * blockDim.x + threadIdx.x;
    if (i < BB * HH) g_gsum[i] = 0.f;
    if (i < BB) g_cnt[i] = 0.f;
}

// input proj; also seeds agg = (1+eps[0])*h0 (fused k_scale for layer 0)
__global__ void k_input(const float* __restrict__ x, const float* __restrict__ W,
                        const float* __restrict__ b, const float* __restrict__ eps) {
    int idx = blockIdx.x * blockDim.x + threadIdx.x;
    if (idx >= NN * HH) return;
    int n = idx >> 7, j = idx & 127;
    const float* xr = x + (size_t)n * NF;
    float acc = b[j];
#pragma unroll
    for (int f = 0; f < NF; f++) acc += xr[f] * W[f * HH + j];
    g_hcat[(size_t)n * 512 + j] = acc;
    g_agg[idx] = (1.f + eps[0]) * acc;
}

// one warp per edge: fused edge-proj + gather(h[src]) + atomic scatter to agg[dst]
__global__ void k_edge(const int* __restrict__ ei, const float* __restrict__ ea,
                       const float* __restrict__ eW, const float* __restrict__ eb,
                       int layer) {
    int warp = (blockIdx.x * blockDim.x + threadIdx.x) >> 5;
    int lane = threadIdx.x & 31;
    if (warp >= EE) return;
    int src = ei[warp];
    int dst = ei[EE + warp];
    float a0 = ea[warp * 3 + 0], a1 = ea[warp * 3 + 1], a2 = ea[warp * 3 + 2];
    const float* W = eW + layer * EF * HH;
    const float* bb = eb + layer * HH;
    int j = lane * 4;
    float4 hv = *(const float4*)(g_hcat + (size_t)src * 512 + layer * HH + j);
    float4 w0 = *(const float4*)(W + 0 * HH + j);
    float4 w1 = *(const float4*)(W + 1 * HH + j);
    float4 w2 = *(const float4*)(W + 2 * HH + j);
    float4 bv = *(const float4*)(bb + j);
    float c0 = hv.x + bv.x + a0 * w0.x + a1 * w1.x + a2 * w2.x;
    float c1 = hv.y + bv.y + a0 * w0.y + a1 * w1.y + a2 * w2.y;
    float c2 = hv.z + bv.z + a0 * w0.z + a1 * w1.z + a2 * w2.z;
    float c3 = hv.w + bv.w + a0 * w0.w + a1 * w1.w + a2 * w2.w;
    float* out = g_agg + (size_t)dst * HH + j;
    atomicAdd(out + 0, c0);
    atomicAdd(out + 1, c1);
    atomicAdd(out + 2, c2);
    atomicAdd(out + 3, c3);
}

// ---------------- tf32 tensor-core GEMM with fused epilogues ------------------
// EPI 0: bn+relu        (mlp1)
// EPI 1: bn+relu + h    (mlp2, writes pre-LN)
// EPI 2: relu           (out1)
// EPI 3: none           (out2)
// Warp tile: 32(M) x 64(N) = 2 x 8 frags of m16n8k8.
// NC==128: 4 M-warps x 2 N-warps, BM=128.  NC==256: 2 x 4, BM=64.
template <int K, int NC, int EPI>
__global__ void __launch_bounds__(256, 2)
k_gemm(const float* __restrict__ A, const float* __restrict__ W,
       const float* __restrict__ bias,
       const float* __restrict__ bng, const float* __restrict__ bnb,
       const float* __restrict__ bnrm, const float* __restrict__ bnrv,
       const float* __restrict__ hres, float* __restrict__ out) {
    constexpr int NW_ = NC / 64;        // N-warps (2 or 4)
    constexpr int MW_ = 8 / NW_;        // M-warps (4 or 2)
    constexpr int BM = MW_ * 32;        // 128 or 64
    constexpr int SA = 36;              // A smem stride (bank = lane, conflict-free)
    constexpr int SB = NC + 8;          // B smem stride (bank = 8k+n, conflict-free)

    __shared__ uint32_t As[BM * SA];
    __shared__ uint32_t Bs[32 * SB];

    int t = threadIdx.x;
    int lane = t & 31, wid = t >> 5;
    int mw = (NC == 128) ? (wid >> 1) : (wid >> 2);
    int nw = (NC == 128) ? (wid & 1) : (wid & 3);
    int wrow = mw * 32, wcol = nw * 64;
    int lr = lane >> 2, lc = lane & 3;
    int n0 = blockIdx.x * BM;

    float acc[2][8][4];
#pragma unroll
    for (int mt = 0; mt < 2; mt++)
#pragma unroll
        for (int nt = 0; nt < 8; nt++)
#pragma unroll
            for (int i = 0; i < 4; i++) acc[mt][nt][i] = 0.f;

    for (int k0 = 0; k0 < K; k0 += 32) {
        // A tile: BM x 32 fp32 -> tf32, stride SA
#pragma unroll
        for (int i = 0; i < (BM * 8) / 256; i++) {
            int f = t + i * 256;
            int r = f >> 3, c4 = f & 7;
            int n = n0 + r;
            float4 v = make_float4(0.f, 0.f, 0.f, 0.f);
            if (n < NN) v = *(const float4*)(A + (size_t)n * K + k0 + c4 * 4);
            uint32_t* d = As + r * SA + c4 * 4;
            d[0] = f2tf(v.x); d[1] = f2tf(v.y); d[2] = f2tf(v.z); d[3] = f2tf(v.w);
        }
        // B tile: 32 x NC fp32 -> tf32, stride SB
#pragma unroll
        for (int i = 0; i < (32 * NC / 4) / 256; i++) {
            int f = t + i * 256;
            int r = f / (NC / 4), c4 = f % (NC / 4);
            float4 v = *(const float4*)(W + (size_t)(k0 + r) * NC + c4 * 4);
            uint32_t* d = Bs + r * SB + c4 * 4;
            d[0] = f2tf(v.x); d[1] = f2tf(v.y); d[2] = f2tf(v.z); d[3] = f2tf(v.w);
        }
        __syncthreads();
#pragma unroll
        for (int ks = 0; ks < 4; ks++) {
            int kk = ks * 8;
            uint32_t a[2][4];
#pragma unroll
            for (int mt = 0; mt < 2; mt++) {
                int base = (wrow + mt * 16 + lr) * SA + kk + lc;
                a[mt][0] = As[base];
                a[mt][1] = As[base + 8 * SA];
                a[mt][2] = As[base + 4];
                a[mt][3] = As[base + 8 * SA + 4];
            }
            uint32_t b[8][2];
#pragma unroll
            for (int nt = 0; nt < 8; nt++) {
                int rb = (kk + lc) * SB + wcol + nt * 8 + lr;
                b[nt][0] = Bs[rb];
                b[nt][1] = Bs[rb + 4 * SB];
            }
#pragma unroll
            for (int mt = 0; mt < 2; mt++)
#pragma unroll
                for (int nt = 0; nt < 8; nt++)
                    mma_tf32(acc[mt][nt], a[mt], b[nt]);
        }
        __syncthreads();
    }

    // epilogue params per (nt, q) column
    float bsv[8][2], sc[8][2], sh[8][2];
#pragma unroll
    for (int nt = 0; nt < 8; nt++)
#pragma unroll
        for (int q = 0; q < 2; q++) {
            int col = wcol + nt * 8 + lc * 2 + q;
            bsv[nt][q] = bias[col];
            if (EPI == 0 || EPI == 1) {
                float s = bng[col] * rsqrtf(bnrv[col] + BN_EPS);
                sc[nt][q] = s;
                sh[nt][q] = bnb[col] - bnrm[col] * s;
            }
        }
#pragma unroll
    for (int mt = 0; mt < 2; mt++)
#pragma unroll
        for (int half = 0; half < 2; half++) {
            int row = wrow + mt * 16 + lr + half * 8;
            int n = n0 + row;
            if (n >= NN) continue;
#pragma unroll
            for (int nt = 0; nt < 8; nt++)
#pragma unroll
                for (int q = 0; q < 2; q++) {
                    int col = wcol + nt * 8 + lc * 2 + q;
                    float v = acc[mt][nt][half * 2 + q] + bsv[nt][q];
                    if (EPI == 0 || EPI == 1) v = fmaxf(v * sc[nt][q] + sh[nt][q], 0.f);
                    if (EPI == 1) v += hres[(size_t)n * 512 + col];
                    if (EPI == 2) v = fmaxf(v, 0.f);
                    out[(size_t)n * NC + col] = v;
                }
        }
}

// LayerNorm over pre-LN buffer (g_agg); writes hcat slot layer+1 and, if another
// layer follows, re-seeds g_agg = (1+eps[layer+1]) * h_{layer+1} (fused k_scale)
__global__ void k_ln(const float* __restrict__ lng, const float* __restrict__ lnb,
                     const float* __restrict__ eps, int layer) {
    int node = (blockIdx.x * blockDim.x + threadIdx.x) >> 5;
    if (node >= NN) return;
    int lane = threadIdx.x & 31;
    float4 v = *(const float4*)(g_agg + (size_t)node * HH + lane * 4);
    float s = v.x + v.y + v.z + v.w;
#pragma unroll
    for (int o = 16; o > 0; o >>= 1) s += __shfl_xor_sync(0xffffffffu, s, o);
    float mu = s * (1.f / 128.f);
    float dx = v.x - mu, dy = v.y - mu, dz = v.z - mu, dw = v.w - mu;
    float q = dx * dx + dy * dy + dz * dz + dw * dw;
#pragma unroll
    for (int o = 16; o > 0; o >>= 1) q += __shfl_xor_sync(0xffffffffu, q, o);
    float inv = rsqrtf(q * (1.f / 128.f) + LN_EPS);
    int j = lane * 4;
    float4 g = *(const float4*)(lng + layer * HH + j);
    float4 b = *(const float4*)(lnb + layer * HH + j);
    float4 o4;
    o4.x = dx * inv * g.x + b.x;
    o4.y = dy * inv * g.y + b.y;
    o4.z = dz * inv * g.z + b.z;
    o4.w = dw * inv * g.w + b.w;
    *(float4*)(g_hcat + (size_t)node * 512 + (layer + 1) * HH + j) = o4;
    if (layer + 1 < LL) {
        float e = 1.f + eps[layer + 1];
        float4 a4 = make_float4(o4.x * e, o4.y * e, o4.z * e, o4.w * e);
        *(float4*)(g_agg + (size_t)node * HH + j) = a4;
    }
}

// pooled sum with run-length pre-aggregation over sorted batch ids
__global__ void k_pool(const int* __restrict__ batch, const float* __restrict__ emb) {
    int c = blockIdx.x;
    int j = threadIdx.x;
    int n0 = c * 32;
    __shared__ int sb[32];
    if (j < 32) sb[j] = (n0 + j < NN) ? batch[n0 + j] : -1;
    __syncthreads();
    float acc = 0.f;
    int bcur = sb[0];
    for (int m = 0; m < 32; m++) {
        int b = sb[m];
        if (b < 0) break;
        if (b != bcur) {
            atomicAdd(&g_gsum[bcur * HH + j], acc);
            acc = 0.f;
            bcur = b;
        }
        acc += emb[(size_t)(n0 + m) * HH + j];
    }
    if (bcur >= 0) atomicAdd(&g_gsum[bcur * HH + j], acc);
    if (j == 0) {
        float cn = 0.f;
        int bc = sb[0];
        for (int m = 0; m < 32; m++) {
            int b = sb[m];
            if (b < 0) break;
            if (b != bc) { atomicAdd(&g_cnt[bc], cn); cn = 0.f; bc = b; }
            cn += 1.f;
        }
        if (bc >= 0) atomicAdd(&g_cnt[bc], cn);
    }
}

__global__ void k_finish(float* __restrict__ out_graph) {
    int i = blockIdx.x * blockDim.x + threadIdx.x;
    if (i >= BB * HH) return;
    out_graph[i] = g_gsum[i] / fmaxf(g_cnt[i >> 7], 1.f);
}

// ---------------- launcher ----------------------------------------------------
extern "C" void kernel_launch(void* const* d_in, const int* in_sizes, int n_in,
                              void* d_out, int out_size) {
    const float* x      = (const float*)d_in[0];
    const int*   ei     = (const int*)  d_in[1];
    const float* ea     = (const float*)d_in[2];
    const int*   batch  = (const int*)  d_in[3];
    const float* in_W   = (const float*)d_in[4];
    const float* in_b   = (const float*)d_in[5];
    const float* edge_W = (const float*)d_in[6];
    const float* edge_b = (const float*)d_in[7];
    const float* mlp_W1 = (const float*)d_in[8];
    const float* mlp_b1 = (const float*)d_in[9];
    const float* bn1_g  = (const float*)d_in[10];
    const float* bn1_b  = (const float*)d_in[11];
    const float* bn1_rm = (const float*)d_in[12];
    const float* bn1_rv = (const float*)d_in[13];
    const float* mlp_W2 = (const float*)d_in[14];
    const float* mlp_b2 = (const float*)d_in[15];
    const float* bn2_g  = (const float*)d_in[16];
    const float* bn2_b  = (const float*)d_in[17];
    const float* bn2_rm = (const float*)d_in[18];
    const float* bn2_rv = (const float*)d_in[19];
    const float* eps    = (const float*)d_in[20];
    const float* ln_g   = (const float*)d_in[21];
    const float* ln_b   = (const float*)d_in[22];
    const float* out_W1 = (const float*)d_in[23];
    const float* out_b1 = (const float*)d_in[24];
    const float* out_W2 = (const float*)d_in[25];
    const float* out_b2 = (const float*)d_in[26];

    float* node_emb  = (float*)d_out;                       // [N, H]
    float* graph_emb = (float*)d_out + (size_t)NN * HH;     // [B, H]

    float* g_hcat_p; cudaGetSymbolAddress((void**)&g_hcat_p, g_hcat);
    float* g_agg_p;  cudaGetSymbolAddress((void**)&g_agg_p,  g_agg);
    float* g_z1_p;   cudaGetSymbolAddress((void**)&g_z1_p,   g_z1);

    const int NT = 256;
    k_zero_pool<<<(BB * HH + NT - 1) / NT, NT>>>();
    k_input<<<(NN * HH + NT - 1) / NT, NT>>>(x, in_W, in_b, eps);

    const int grid128 = (NN + 127) / 128;   // NC=128 configs (BM=128)
    const int grid64  = (NN + 63) / 64;     // NC=256 configs (BM=64)
    for (int l = 0; l < LL; l++) {
        k_edge<<<(EE * 32 + NT - 1) / NT, NT>>>(ei, ea, edge_W, edge_b, l);
        // mlp1: agg[N,128] @ W1 -> z1[N,256], bn1+relu
        k_gemm<128, 256, 0><<<grid64, 256>>>(
            g_agg_p, mlp_W1 + (size_t)l * 128 * 256, mlp_b1 + l * 256,
            bn1_g + l * 256, bn1_b + l * 256, bn1_rm + l * 256, bn1_rv + l * 256,
            nullptr, g_z1_p);
        // mlp2: z1[N,256] @ W2 -> preLN[N,128] (bn2+relu + residual h), into g_agg
        k_gemm<256, 128, 1><<<grid128, 256>>>(
            g_z1_p, mlp_W2 + (size_t)l * 256 * 128, mlp_b2 + l * 128,
            bn2_g + l * 128, bn2_b + l * 128, bn2_rm + l * 128, bn2_rv + l * 128,
            g_hcat_p + l * HH, g_agg_p);
        k_ln<<<(NN * 32 + NT - 1) / NT, NT>>>(ln_g, ln_b, eps, l);
    }
    // out1: hcat[N,512] @ W1 -> relu -> g_z1[N,128]
    k_gemm<512, 128, 2><<<grid128, 256>>>(
        g_hcat_p, out_W1, out_b1, nullptr, nullptr, nullptr, nullptr, nullptr, g_z1_p);
    // out2: g_z1[N,128] @ W2 -> node_emb
    k_gemm<128, 128, 3><<<grid128, 256>>>(
        g_z1_p, out_W2, out_b2, nullptr, nullptr, nullptr, nullptr, nullptr, node_emb);

    k_pool<<<(NN + 31) / 32, 128>>>(batch, node_emb);
    k_finish<<<(BB * HH + NT - 1) / NT, NT>>>(graph_emb);
}

// round 3
// speedup vs baseline: 2.3022x; 1.3183x over previous
#include <cuda_runtime.h>
#include <math.h>
#include <stdint.h>

#define NN 100000
#define EE 600000
#define HH 128
#define LL 3
#define BB 16
#define NF 12
#define EF 3
#define BN_EPS 1e-5f
#define LN_EPS 1e-5f

// weight scratch layout (tf32-converted)
#define W1TF 0                       // L*128*256
#define W2TF (LL * 128 * 256)        // L*256*128
#define O1TF (W2TF + LL * 256 * 128) // 512*128
#define O2TF (O1TF + 512 * 128)      // 128*128
#define WTOT (O2TF + 128 * 128)

// ---------------- scratch (static device globals; no runtime alloc) ----------
__device__ float g_hcat[(size_t)NN * 4 * HH];   // h0..h3 concatenated per node
__device__ float g_agg [(size_t)NN * HH];       // GIN pre-MLP (tf32 bits) / pre-LN (fp32)
__device__ float g_z1  [(size_t)NN * 2 * HH];   // mlp hidden / out1 result (tf32 bits)
__device__ float g_pre [(size_t)NN * HH];       // pre-LN buffer (fp32)
__device__ float g_wtf [WTOT];                  // tf32-converted weights
__device__ float g_gsum[BB * HH];
__device__ float g_cnt [BB];
__device__ int   g_deg [NN];
__device__ int   g_rows[NN];
__device__ int   g_fill[NN];
__device__ int   g_perm[EE];
__device__ int   g_bsum[128];
__device__ int   g_boff[128];

// ---------------- helpers ----------------------------------------------------
__device__ __forceinline__ uint32_t f2tf(float f) {
    uint32_t r;
    asm("cvt.rna.tf32.f32 %0, %1;" : "=r"(r) : "f"(f));
    return r;
}
__device__ __forceinline__ void mma_tf32(float* c, const uint32_t* a, const uint32_t* b) {
    asm volatile(
        "mma.sync.aligned.m16n8k8.row.col.f32.tf32.tf32.f32 "
        "{%0,%1,%2,%3},{%4,%5,%6,%7},{%8,%9},{%0,%1,%2,%3};\n"
        : "+f"(c[0]), "+f"(c[1]), "+f"(c[2]), "+f"(c[3])
        : "r"(a[0]), "r"(a[1]), "r"(a[2]), "r"(a[3]), "r"(b[0]), "r"(b[1]));
}
__device__ __forceinline__ uint32_t sptr(const void* p) {
    return (uint32_t)__cvta_generic_to_shared(p);
}
__device__ __forceinline__ void cp16(uint32_t d, const void* s, int sz) {
    asm volatile("cp.async.cg.shared.global [%0], [%1], 16, %2;\n"
                 :: "r"(d), "l"(s), "r"(sz));
}
__device__ __forceinline__ void cp_commit() {
    asm volatile("cp.async.commit_group;\n" ::: "memory");
}
template <int N> __device__ __forceinline__ void cp_wait() {
    asm volatile("cp.async.wait_group %0;\n" :: "n"(N) : "memory");
}

// ---------------- init / weight convert ---------------------------------------
__global__ void k_init() {
    int i = blockIdx.x * blockDim.x + threadIdx.x;
    if (i < BB * HH) g_gsum[i] = 0.f;
    if (i < BB) g_cnt[i] = 0.f;
    if (i < NN) { g_deg[i] = 0; g_fill[i] = 0; }
}

__global__ void k_wcvt(const float* __restrict__ w1, const float* __restrict__ w2,
                       const float* __restrict__ o1, const float* __restrict__ o2) {
    int i = blockIdx.x * blockDim.x + threadIdx.x;
    if (i >= WTOT) return;
    float v;
    if (i < W2TF) v = w1[i];
    else if (i < O1TF) v = w2[i - W2TF];
    else if (i < O2TF) v = o1[i - O1TF];
    else v = o2[i - O2TF];
    g_wtf[i] = __uint_as_float(f2tf(v));
}

// input proj -> hcat slot 0
__global__ void k_input(const float* __restrict__ x, const float* __restrict__ W,
                        const float* __restrict__ b) {
    int idx = blockIdx.x * blockDim.x + threadIdx.x;
    if (idx >= NN * HH) return;
    int n = idx >> 7, j = idx & 127;
    const float* xr = x + (size_t)n * NF;
    float acc = b[j];
#pragma unroll
    for (int f = 0; f < NF; f++) acc += xr[f] * W[f * HH + j];
    g_hcat[(size_t)n * 512 + j] = acc;
}

// ---------------- CSR build (dst-sorted, once per launch) ---------------------
__global__ void k_count(const int* __restrict__ ei) {
    int e = blockIdx.x * blockDim.x + threadIdx.x;
    if (e < EE) atomicAdd(&g_deg[ei[EE + e]], 1);
}

__global__ void k_scan1() {   // 1024 elems per block, 256 threads x 4
    __shared__ int ss[256];
    int t = threadIdx.x;
    int base = blockIdx.x * 1024;
    int v[4], s = 0;
#pragma unroll
    for (int j = 0; j < 4; j++) {
        int i = base + t * 4 + j;
        v[j] = (i < NN) ? g_deg[i] : 0;
        s += v[j];
    }
    ss[t] = s;
    __syncthreads();
#pragma unroll
    for (int off = 1; off < 256; off <<= 1) {
        int a = (t >= off) ? ss[t - off] : 0;
        __syncthreads();
        ss[t] += a;
        __syncthreads();
    }
    if (t == 255) g_bsum[blockIdx.x] = ss[255];
    int run = ss[t] - s;   // exclusive
#pragma unroll
    for (int j = 0; j < 4; j++) {
        int i = base + t * 4 + j;
        if (i < NN) g_rows[i] = run;
        run += v[j];
    }
}

__global__ void k_scan2(int nb) {  // single block
    __shared__ int ss[128];
    int t = threadIdx.x;
    int v = (t < nb) ? g_bsum[t] : 0;
    ss[t] = v;
    __syncthreads();
#pragma unroll
    for (int off = 1; off < 128; off <<= 1) {
        int a = (t >= off) ? ss[t - off] : 0;
        __syncthreads();
        ss[t] += a;
        __syncthreads();
    }
    if (t < nb) g_boff[t] = ss[t] - v;
}

__global__ void k_scan3() {
    int i = blockIdx.x * blockDim.x + threadIdx.x;
    if (i < NN) g_rows[i] += g_boff[i >> 10];
}

__global__ void k_place(const int* __restrict__ ei) {
    int e = blockIdx.x * blockDim.x + threadIdx.x;
    if (e >= EE) return;
    int d = ei[EE + e];
    int p = g_rows[d] + atomicAdd(&g_fill[d], 1);
    g_perm[p] = e;
}

// ---------------- per-node gather aggregation (no atomics) --------------------
// one warp per dst node: acc = (1+eps)*h[dst] + sum_in( h[src] + eproj(edge) )
// writes g_agg as tf32 bits (consumed only by mlp1 GEMM)
__global__ void k_gather(const int* __restrict__ ei, const float* __restrict__ ea,
                         const float* __restrict__ eW, const float* __restrict__ eb,
                         const float* __restrict__ eps, int layer) {
    int warp = (blockIdx.x * blockDim.x + threadIdx.x) >> 5;
    int lane = threadIdx.x & 31;
    if (warp >= NN) return;
    int j = lane * 4;
    const float* W = eW + layer * EF * HH;
    float4 w0 = *(const float4*)(W + 0 * HH + j);
    float4 w1 = *(const float4*)(W + 1 * HH + j);
    float4 w2 = *(const float4*)(W + 2 * HH + j);
    float4 bv = *(const float4*)(eb + layer * HH + j);
    const float* hl = g_hcat + (size_t)layer * HH;
    float4 hd = *(const float4*)(hl + (size_t)warp * 512 + j);
    float e1 = 1.f + eps[layer];
    float ax = e1 * hd.x, ay = e1 * hd.y, az = e1 * hd.z, aw = e1 * hd.w;
    int start = g_rows[warp], deg = g_deg[warp];
    for (int k = 0; k < deg; k++) {
        int e = g_perm[start + k];
        int src = ei[e];
        float a0 = ea[e * 3 + 0], a1 = ea[e * 3 + 1], a2 = ea[e * 3 + 2];
        float4 hv = *(const float4*)(hl + (size_t)src * 512 + j);
        ax += hv.x + bv.x + a0 * w0.x + a1 * w1.x + a2 * w2.x;
        ay += hv.y + bv.y + a0 * w0.y + a1 * w1.y + a2 * w2.y;
        az += hv.z + bv.z + a0 * w0.z + a1 * w1.z + a2 * w2.z;
        aw += hv.w + bv.w + a0 * w0.w + a1 * w1.w + a2 * w2.w;
    }
    float4 o;
    o.x = __uint_as_float(f2tf(ax));
    o.y = __uint_as_float(f2tf(ay));
    o.z = __uint_as_float(f2tf(az));
    o.w = __uint_as_float(f2tf(aw));
    *(float4*)(g_agg + (size_t)warp * HH + j) = o;
}

// ---------------- tf32 tensor-core GEMM, cp.async double-buffered -------------
// EPI 0: bn+relu, write tf32        (mlp1 -> z1)
// EPI 1: bn+relu + h, write fp32    (mlp2 -> pre-LN)
// EPI 2: relu, write tf32           (out1 -> g_z1)
// EPI 3: none, write fp32           (out2 -> node_emb)
// CVTA=1: A in fp32, convert at fragment load (out1 only)
template <int K, int NC, int EPI, int CVTA>
__global__ void __launch_bounds__(256, 2)
k_gemm(const float* __restrict__ A, const float* __restrict__ Wt,
       const float* __restrict__ bias,
       const float* __restrict__ bng, const float* __restrict__ bnb,
       const float* __restrict__ bnrm, const float* __restrict__ bnrv,
       const float* __restrict__ hres, float* __restrict__ out) {
    constexpr int NW_ = NC / 64;
    constexpr int MW_ = 8 / NW_;
    constexpr int BM = MW_ * 32;
    constexpr int KC = 16;
    constexpr int SA = 20;            // bank-perm pad (20 ≡ 4·odd mod 32)
    constexpr int SB = NC + 8;
    constexpr int CH = K / KC;

    __shared__ float As[2][BM * SA];
    __shared__ float Bs[2][KC * SB];

    int t = threadIdx.x;
    int lane = t & 31, wid = t >> 5;
    int mw = (NC == 128) ? (wid >> 1) : (wid >> 2);
    int nw = (NC == 128) ? (wid & 1) : (wid & 3);
    int wrow = mw * 32, wcol = nw * 64;
    int lr = lane >> 2, lc = lane & 3;
    int n0 = blockIdx.x * BM;

    float acc[2][8][4];
#pragma unroll
    for (int mt = 0; mt < 2; mt++)
#pragma unroll
        for (int nt = 0; nt < 8; nt++)
#pragma unroll
            for (int i = 0; i < 4; i++) acc[mt][nt][i] = 0.f;

    auto load_tiles = [&](int k0, int st) {
#pragma unroll
        for (int i = 0; i < BM / 64; i++) {      // BM*KC/4/256
            int f = t + i * 256;
            int r = f >> 2, c4 = f & 3;
            int n = n0 + r;
            const float* src = A + (size_t)(n < NN ? n : 0) * K + k0 + c4 * 4;
            cp16(sptr(&As[st][r * SA + c4 * 4]), src, n < NN ? 16 : 0);
        }
#pragma unroll
        for (int i = 0; i < NC / 64; i++) {      // KC*NC/4/256
            int f = t + i * 256;
            int r = f / (NC / 4), c4 = f % (NC / 4);
            cp16(sptr(&Bs[st][r * SB + c4 * 4]), Wt + (size_t)(k0 + r) * NC + c4 * 4, 16);
        }
    };

    load_tiles(0, 0);
    cp_commit();
    for (int c = 0; c < CH; c++) {
        int st = c & 1;
        if (c + 1 < CH) {
            load_tiles((c + 1) * KC, st ^ 1);
            cp_commit();
            cp_wait<1>();
        } else {
            cp_wait<0>();
        }
        __syncthreads();
#pragma unroll
        for (int ks = 0; ks < 2; ks++) {
            int kk = ks * 8;
            uint32_t a[2][4];
#pragma unroll
            for (int mt = 0; mt < 2; mt++) {
                int base = (wrow + mt * 16 + lr) * SA + kk + lc;
                if (CVTA) {
                    a[mt][0] = f2tf(As[st][base]);
                    a[mt][1] = f2tf(As[st][base + 8 * SA]);
                    a[mt][2] = f2tf(As[st][base + 4]);
                    a[mt][3] = f2tf(As[st][base + 8 * SA + 4]);
                } else {
                    a[mt][0] = __float_as_uint(As[st][base]);
                    a[mt][1] = __float_as_uint(As[st][base + 8 * SA]);
                    a[mt][2] = __float_as_uint(As[st][base + 4]);
                    a[mt][3] = __float_as_uint(As[st][base + 8 * SA + 4]);
                }
            }
            uint32_t b[8][2];
#pragma unroll
            for (int nt = 0; nt < 8; nt++) {
                int rb = (kk + lc) * SB + wcol + nt * 8 + lr;
                b[nt][0] = __float_as_uint(Bs[st][rb]);
                b[nt][1] = __float_as_uint(Bs[st][rb + 4 * SB]);
            }
#pragma unroll
            for (int mt = 0; mt < 2; mt++)
#pragma unroll
                for (int nt = 0; nt < 8; nt++)
                    mma_tf32(acc[mt][nt], a[mt], b[nt]);
        }
        __syncthreads();
    }

    float bsv[8][2], sc[8][2], sh[8][2];
#pragma unroll
    for (int nt = 0; nt < 8; nt++)
#pragma unroll
        for (int q = 0; q < 2; q++) {
            int col = wcol + nt * 8 + lc * 2 + q;
            bsv[nt][q] = bias[col];
            if (EPI == 0 || EPI == 1) {
                float s = bng[col] * rsqrtf(bnrv[col] + BN_EPS);
                sc[nt][q] = s;
                sh[nt][q] = bnb[col] - bnrm[col] * s;
            }
        }
#pragma unroll
    for (int mt = 0; mt < 2; mt++)
#pragma unroll
        for (int half = 0; half < 2; half++) {
            int row = wrow + mt * 16 + lr + half * 8;
            int n = n0 + row;
            if (n >= NN) continue;
#pragma unroll
            for (int nt = 0; nt < 8; nt++)
#pragma unroll
                for (int q = 0; q < 2; q++) {
                    int col = wcol + nt * 8 + lc * 2 + q;
                    float v = acc[mt][nt][half * 2 + q] + bsv[nt][q];
                    if (EPI == 0 || EPI == 1) v = fmaxf(v * sc[nt][q] + sh[nt][q], 0.f);
                    if (EPI == 1) v += hres[(size_t)n * 512 + col];
                    if (EPI == 2) v = fmaxf(v, 0.f);
                    if (EPI == 0 || EPI == 2) v = __uint_as_float(f2tf(v));
                    out[(size_t)n * NC + col] = v;
                }
        }
}

// LayerNorm over pre-LN buffer (g_pre); writes hcat slot layer+1
__global__ void k_ln(const float* __restrict__ lng, const float* __restrict__ lnb,
                     int layer) {
    int node = (blockIdx.x * blockDim.x + threadIdx.x) >> 5;
    if (node >= NN) return;
    int lane = threadIdx.x & 31;
    float4 v = *(const float4*)(g_pre + (size_t)node * HH + lane * 4);
    float s = v.x + v.y + v.z + v.w;
#pragma unroll
    for (int o = 16; o > 0; o >>= 1) s += __shfl_xor_sync(0xffffffffu, s, o);
    float mu = s * (1.f / 128.f);
    float dx = v.x - mu, dy = v.y - mu, dz = v.z - mu, dw = v.w - mu;
    float q = dx * dx + dy * dy + dz * dz + dw * dw;
#pragma unroll
    for (int o = 16; o > 0; o >>= 1) q += __shfl_xor_sync(0xffffffffu, q, o);
    float inv = rsqrtf(q * (1.f / 128.f) + LN_EPS);
    int j = lane * 4;
    float4 g = *(const float4*)(lng + layer * HH + j);
    float4 b = *(const float4*)(lnb + layer * HH + j);
    float4 o4;
    o4.x = dx * inv * g.x + b.x;
    o4.y = dy * inv * g.y + b.y;
    o4.z = dz * inv * g.z + b.z;
    o4.w = dw * inv * g.w + b.w;
    *(float4*)(g_hcat + (size_t)node * 512 + (layer + 1) * HH + j) = o4;
}

// pooled sum with run-length pre-aggregation over sorted batch ids
__global__ void k_pool(const int* __restrict__ batch, const float* __restrict__ emb) {
    int c = blockIdx.x;
    int j = threadIdx.x;
    int n0 = c * 32;
    __shared__ int sb[32];
    if (j < 32) sb[j] = (n0 + j < NN) ? batch[n0 + j] : -1;
    __syncthreads();
    float acc = 0.f;
    int bcur = sb[0];
    for (int m = 0; m < 32; m++) {
        int b = sb[m];
        if (b < 0) break;
        if (b != bcur) {
            atomicAdd(&g_gsum[bcur * HH + j], acc);
            acc = 0.f;
            bcur = b;
        }
        acc += emb[(size_t)(n0 + m) * HH + j];
    }
    if (bcur >= 0) atomicAdd(&g_gsum[bcur * HH + j], acc);
    if (j == 0) {
        float cn = 0.f;
        int bc = sb[0];
        for (int m = 0; m < 32; m++) {
            int b = sb[m];
            if (b < 0) break;
            if (b != bc) { atomicAdd(&g_cnt[bc], cn); cn = 0.f; bc = b; }
            cn += 1.f;
        }
        if (bc >= 0) atomicAdd(&g_cnt[bc], cn);
    }
}

__global__ void k_finish(float* __restrict__ out_graph) {
    int i = blockIdx.x * blockDim.x + threadIdx.x;
    if (i >= BB * HH) return;
    out_graph[i] = g_gsum[i] / fmaxf(g_cnt[i >> 7], 1.f);
}

// ---------------- launcher ----------------------------------------------------
extern "C" void kernel_launch(void* const* d_in, const int* in_sizes, int n_in,
                              void* d_out, int out_size) {
    const float* x      = (const float*)d_in[0];
    const int*   ei     = (const int*)  d_in[1];
    const float* ea     = (const float*)d_in[2];
    const int*   batch  = (const int*)  d_in[3];
    const float* in_W   = (const float*)d_in[4];
    const float* in_b   = (const float*)d_in[5];
    const float* edge_W = (const float*)d_in[6];
    const float* edge_b = (const float*)d_in[7];
    const float* mlp_W1 = (const float*)d_in[8];
    const float* mlp_b1 = (const float*)d_in[9];
    const float* bn1_g  = (const float*)d_in[10];
    const float* bn1_b  = (const float*)d_in[11];
    const float* bn1_rm = (const float*)d_in[12];
    const float* bn1_rv = (const float*)d_in[13];
    const float* mlp_W2 = (const float*)d_in[14];
    const float* mlp_b2 = (const float*)d_in[15];
    const float* bn2_g  = (const float*)d_in[16];
    const float* bn2_b  = (const float*)d_in[17];
    const float* bn2_rm = (const float*)d_in[18];
    const float* bn2_rv = (const float*)d_in[19];
    const float* eps    = (const float*)d_in[20];
    const float* ln_g   = (const float*)d_in[21];
    const float* ln_b   = (const float*)d_in[22];
    const float* out_W1 = (const float*)d_in[23];
    const float* out_b1 = (const float*)d_in[24];
    const float* out_W2 = (const float*)d_in[25];
    const float* out_b2 = (const float*)d_in[26];

    float* node_emb  = (float*)d_out;                       // [N, H]
    float* graph_emb = (float*)d_out + (size_t)NN * HH;     // [B, H]

    float* g_hcat_p; cudaGetSymbolAddress((void**)&g_hcat_p, g_hcat);
    float* g_agg_p;  cudaGetSymbolAddress((void**)&g_agg_p,  g_agg);
    float* g_z1_p;   cudaGetSymbolAddress((void**)&g_z1_p,   g_z1);
    float* g_pre_p;  cudaGetSymbolAddress((void**)&g_pre_p,  g_pre);
    float* g_wtf_p;  cudaGetSymbolAddress((void**)&g_wtf_p,  g_wtf);

    const int NT = 256;
    k_init<<<(NN + NT - 1) / NT, NT>>>();
    k_wcvt<<<(WTOT + NT - 1) / NT, NT>>>(mlp_W1, mlp_W2, out_W1, out_W2);
    k_input<<<(NN * HH + NT - 1) / NT, NT>>>(x, in_W, in_b);

    // CSR build (edge list shared across layers)
    k_count<<<(EE + NT - 1) / NT, NT>>>(ei);
    k_scan1<<<(NN + 1023) / 1024, 256>>>();
    k_scan2<<<1, 128>>>((NN + 1023) / 1024);
    k_scan3<<<(NN + NT - 1) / NT, NT>>>();
    k_place<<<(EE + NT - 1) / NT, NT>>>(ei);

    const int grid128 = (NN + 127) / 128;   // NC=128 configs (BM=128)
    const int grid64  = (NN + 63) / 64;     // NC=256 configs (BM=64)
    for (int l = 0; l < LL; l++) {
        k_gather<<<(NN * 32 + NT - 1) / NT, NT>>>(ei, ea, edge_W, edge_b, eps, l);
        // mlp1: agg[N,128](tf32) @ W1 -> z1[N,256] tf32, bn1+relu
        k_gemm<128, 256, 0, 0><<<grid64, 256>>>(
            g_agg_p, g_wtf_p + W1TF + (size_t)l * 128 * 256, mlp_b1 + l * 256,
            bn1_g + l * 256, bn1_b + l * 256, bn1_rm + l * 256, bn1_rv + l * 256,
            nullptr, g_z1_p);
        // mlp2: z1[N,256](tf32) @ W2 -> pre-LN fp32 (bn2+relu + residual h)
        k_gemm<256, 128, 1, 0><<<grid128, 256>>>(
            g_z1_p, g_wtf_p + W2TF + (size_t)l * 256 * 128, mlp_b2 + l * 128,
            bn2_g + l * 128, bn2_b + l * 128, bn2_rm + l * 128, bn2_rv + l * 128,
            g_hcat_p + l * HH, g_pre_p);
        k_ln<<<(NN * 32 + NT - 1) / NT, NT>>>(ln_g, ln_b, l);
    }
    // out1: hcat[N,512](fp32, CVTA) @ W1 -> relu -> g_z1[N,128] tf32
    k_gemm<512, 128, 2, 1><<<grid128, 256>>>(
        g_hcat_p, g_wtf_p + O1TF, out_b1, nullptr, nullptr, nullptr, nullptr,
        nullptr, g_z1_p);
    // out2: g_z1[N,128](tf32) @ W2 -> node_emb fp32
    k_gemm<128, 128, 3, 0><<<grid128, 256>>>(
        g_z1_p, g_wtf_p + O2TF, out_b2, nullptr, nullptr, nullptr, nullptr,
        nullptr, node_emb);

    k_pool<<<(NN + 31) / 32, 128>>>(batch, node_emb);
    k_finish<<<(BB * HH + NT - 1) / NT, NT>>>(graph_emb);
}

// round 4
// speedup vs baseline: 2.4501x; 1.0642x over previous
#include <cuda_runtime.h>
#include <math.h>
#include <stdint.h>

#define NN 100000
#define EE 600000
#define HH 128
#define LL 3
#define BB 16
#define NF 12
#define EF 3
#define BN_EPS 1e-5f
#define LN_EPS 1e-5f

// weight scratch layout (tf32-converted)
#define W1TF 0                       // L*128*256
#define W2TF (LL * 128 * 256)        // L*256*128
#define O1TF (W2TF + LL * 256 * 128) // 512*128
#define O2TF (O1TF + 512 * 128)      // 128*128
#define WTOT (O2TF + 128 * 128)

// ---------------- scratch (static device globals; no runtime alloc) ----------
__device__ float g_hcat[(size_t)NN * 4 * HH];   // h0..h3 concatenated per node
__device__ float g_agg [(size_t)NN * HH];       // GIN pre-MLP (tf32 bits)
__device__ float g_z1  [(size_t)NN * 2 * HH];   // mlp hidden / out1 result (tf32 bits)
__device__ float g_wtf [WTOT];                  // tf32-converted weights
__device__ float g_gsum[BB * HH];
__device__ float g_cnt [BB];
__device__ int   g_deg [NN];
__device__ int   g_rows[NN];
__device__ int   g_fill[NN];
__device__ float4 g_epack[EE];                  // {src_bits, a0, a1, a2} CSR order
__device__ int   g_bsum[128];
__device__ int   g_boff[128];

// ---------------- helpers ----------------------------------------------------
__device__ __forceinline__ uint32_t f2tf(float f) {
    uint32_t r;
    asm("cvt.rna.tf32.f32 %0, %1;" : "=r"(r) : "f"(f));
    return r;
}
__device__ __forceinline__ void mma_tf32(float* c, const uint32_t* a, const uint32_t* b) {
    asm volatile(
        "mma.sync.aligned.m16n8k8.row.col.f32.tf32.tf32.f32 "
        "{%0,%1,%2,%3},{%4,%5,%6,%7},{%8,%9},{%0,%1,%2,%3};\n"
        : "+f"(c[0]), "+f"(c[1]), "+f"(c[2]), "+f"(c[3])
        : "r"(a[0]), "r"(a[1]), "r"(a[2]), "r"(a[3]), "r"(b[0]), "r"(b[1]));
}
__device__ __forceinline__ uint32_t sptr(const void* p) {
    return (uint32_t)__cvta_generic_to_shared(p);
}
__device__ __forceinline__ void cp16(uint32_t d, const void* s, int sz) {
    asm volatile("cp.async.cg.shared.global [%0], [%1], 16, %2;\n"
                 :: "r"(d), "l"(s), "r"(sz));
}
__device__ __forceinline__ void cp_commit() {
    asm volatile("cp.async.commit_group;\n" ::: "memory");
}
template <int N> __device__ __forceinline__ void cp_wait() {
    asm volatile("cp.async.wait_group %0;\n" :: "n"(N) : "memory");
}

// ---------------- init / weight convert ---------------------------------------
__global__ void k_init() {
    int i = blockIdx.x * blockDim.x + threadIdx.x;
    if (i < BB * HH) g_gsum[i] = 0.f;
    if (i < BB) g_cnt[i] = 0.f;
    if (i < NN) { g_deg[i] = 0; g_fill[i] = 0; }
}

__global__ void k_wcvt(const float* __restrict__ w1, const float* __restrict__ w2,
                       const float* __restrict__ o1, const float* __restrict__ o2) {
    int i = blockIdx.x * blockDim.x + threadIdx.x;
    if (i >= WTOT) return;
    float v;
    if (i < W2TF) v = w1[i];
    else if (i < O1TF) v = w2[i - W2TF];
    else if (i < O2TF) v = o1[i - O1TF];
    else v = o2[i - O2TF];
    g_wtf[i] = __uint_as_float(f2tf(v));
}

// input proj -> hcat slot 0
__global__ void k_input(const float* __restrict__ x, const float* __restrict__ W,
                        const float* __restrict__ b) {
    int idx = blockIdx.x * blockDim.x + threadIdx.x;
    if (idx >= NN * HH) return;
    int n = idx >> 7, j = idx & 127;
    const float* xr = x + (size_t)n * NF;
    float acc = b[j];
#pragma unroll
    for (int f = 0; f < NF; f++) acc += xr[f] * W[f * HH + j];
    g_hcat[(size_t)n * 512 + j] = acc;
}

// ---------------- CSR build (dst-sorted, once per launch) ---------------------
__global__ void k_count(const int* __restrict__ ei) {
    int e = blockIdx.x * blockDim.x + threadIdx.x;
    if (e < EE) atomicAdd(&g_deg[ei[EE + e]], 1);
}

__global__ void k_scan1() {   // 1024 elems per block, 256 threads x 4
    __shared__ int ss[256];
    int t = threadIdx.x;
    int base = blockIdx.x * 1024;
    int v[4], s = 0;
#pragma unroll
    for (int j = 0; j < 4; j++) {
        int i = base + t * 4 + j;
        v[j] = (i < NN) ? g_deg[i] : 0;
        s += v[j];
    }
    ss[t] = s;
    __syncthreads();
#pragma unroll
    for (int off = 1; off < 256; off <<= 1) {
        int a = (t >= off) ? ss[t - off] : 0;
        __syncthreads();
        ss[t] += a;
        __syncthreads();
    }
    if (t == 255) g_bsum[blockIdx.x] = ss[255];
    int run = ss[t] - s;   // exclusive
#pragma unroll
    for (int j = 0; j < 4; j++) {
        int i = base + t * 4 + j;
        if (i < NN) g_rows[i] = run;
        run += v[j];
    }
}

__global__ void k_scan2(int nb) {  // single block
    __shared__ int ss[128];
    int t = threadIdx.x;
    int v = (t < nb) ? g_bsum[t] : 0;
    ss[t] = v;
    __syncthreads();
#pragma unroll
    for (int off = 1; off < 128; off <<= 1) {
        int a = (t >= off) ? ss[t - off] : 0;
        __syncthreads();
        ss[t] += a;
        __syncthreads();
    }
    if (t < nb) g_boff[t] = ss[t] - v;
}

__global__ void k_scan3() {
    int i = blockIdx.x * blockDim.x + threadIdx.x;
    if (i < NN) g_rows[i] += g_boff[i >> 10];
}

// place packed edge record {src, a0, a1, a2} in CSR slot
__global__ void k_place(const int* __restrict__ ei, const float* __restrict__ ea) {
    int e = blockIdx.x * blockDim.x + threadIdx.x;
    if (e >= EE) return;
    int d = ei[EE + e];
    int p = g_rows[d] + atomicAdd(&g_fill[d], 1);
    float4 r;
    r.x = __int_as_float(ei[e]);
    r.y = ea[e * 3 + 0];
    r.z = ea[e * 3 + 1];
    r.w = ea[e * 3 + 2];
    g_epack[p] = r;
}

// ---------------- per-node gather aggregation (no atomics) --------------------
// one warp per dst node: acc = (1+eps)*h[dst] + deg*bias + sum_in(h[src] + ea@W)
// writes g_agg as tf32 bits (consumed only by mlp1 GEMM)
__global__ void k_gather(const float* __restrict__ eW, const float* __restrict__ eb,
                         const float* __restrict__ eps, int layer) {
    int warp = (blockIdx.x * blockDim.x + threadIdx.x) >> 5;
    int lane = threadIdx.x & 31;
    if (warp >= NN) return;
    int j = lane * 4;
    const float* W = eW + layer * EF * HH;
    float4 w0 = *(const float4*)(W + 0 * HH + j);
    float4 w1 = *(const float4*)(W + 1 * HH + j);
    float4 w2 = *(const float4*)(W + 2 * HH + j);
    float4 bv = *(const float4*)(eb + layer * HH + j);
    const float* hl = g_hcat + (size_t)layer * HH;
    float4 hd = *(const float4*)(hl + (size_t)warp * 512 + j);
    int start = g_rows[warp], deg = g_deg[warp];
    const float4* ep = g_epack + start;

    float e1 = 1.f + eps[layer];
    float dg = (float)deg;
    float ax = e1 * hd.x + dg * bv.x;
    float ay = e1 * hd.y + dg * bv.y;
    float az = e1 * hd.z + dg * bv.z;
    float aw = e1 * hd.w + dg * bv.w;
    float bx = 0.f, by = 0.f, bz = 0.f, bw = 0.f;

    int k = 0;
    for (; k + 2 <= deg; k += 2) {
        float4 r0 = ep[k], r1 = ep[k + 1];
        int s0 = __float_as_int(r0.x), s1 = __float_as_int(r1.x);
        float4 h0 = *(const float4*)(hl + (size_t)s0 * 512 + j);
        float4 h1 = *(const float4*)(hl + (size_t)s1 * 512 + j);
        ax += h0.x + r0.y * w0.x + r0.z * w1.x + r0.w * w2.x;
        ay += h0.y + r0.y * w0.y + r0.z * w1.y + r0.w * w2.y;
        az += h0.z + r0.y * w0.z + r0.z * w1.z + r0.w * w2.z;
        aw += h0.w + r0.y * w0.w + r0.z * w1.w + r0.w * w2.w;
        bx += h1.x + r1.y * w0.x + r1.z * w1.x + r1.w * w2.x;
        by += h1.y + r1.y * w0.y + r1.z * w1.y + r1.w * w2.y;
        bz += h1.z + r1.y * w0.z + r1.z * w1.z + r1.w * w2.z;
        bw += h1.w + r1.y * w0.w + r1.z * w1.w + r1.w * w2.w;
    }
    if (k < deg) {
        float4 r0 = ep[k];
        int s0 = __float_as_int(r0.x);
        float4 h0 = *(const float4*)(hl + (size_t)s0 * 512 + j);
        ax += h0.x + r0.y * w0.x + r0.z * w1.x + r0.w * w2.x;
        ay += h0.y + r0.y * w0.y + r0.z * w1.y + r0.w * w2.y;
        az += h0.z + r0.y * w0.z + r0.z * w1.z + r0.w * w2.z;
        aw += h0.w + r0.y * w0.w + r0.z * w1.w + r0.w * w2.w;
    }
    float4 o;
    o.x = __uint_as_float(f2tf(ax + bx));
    o.y = __uint_as_float(f2tf(ay + by));
    o.z = __uint_as_float(f2tf(az + bz));
    o.w = __uint_as_float(f2tf(aw + bw));
    *(float4*)(g_agg + (size_t)warp * HH + j) = o;
}

// ---------------- tf32 tensor-core GEMM, cp.async double-buffered -------------
// EPI 0: bn+relu, write tf32                        (mlp1 -> z1)
// EPI 1: bn+relu + h, then fused LayerNorm -> hcat  (mlp2; out stride 512)
// EPI 2: relu, write tf32                           (out1 -> g_z1)
// EPI 3: none, write fp32                           (out2 -> node_emb)
// CVTA=1: A in fp32, convert at fragment load (out1 only)
template <int K, int NC, int EPI, int CVTA>
__global__ void __launch_bounds__(256, 2)
k_gemm(const float* __restrict__ A, const float* __restrict__ Wt,
       const float* __restrict__ bias,
       const float* __restrict__ bng, const float* __restrict__ bnb,
       const float* __restrict__ bnrm, const float* __restrict__ bnrv,
       const float* __restrict__ hres,
       const float* __restrict__ lng, const float* __restrict__ lnb,
       float* __restrict__ out) {
    constexpr int NW_ = NC / 64;
    constexpr int MW_ = 8 / NW_;
    constexpr int BM = MW_ * 32;
    constexpr int KC = 16;
    constexpr int SA = 20;
    constexpr int SB = NC + 8;
    constexpr int CH = K / KC;
    constexpr int OS = (EPI == 1) ? 512 : NC;   // output row stride

    __shared__ float As[2][BM * SA];
    __shared__ float Bs[2][KC * SB];
    __shared__ float red[(EPI == 1) ? (BM * 2 * 2) : 4];  // [row][nw][{sum,sumsq}]

    int t = threadIdx.x;
    int lane = t & 31, wid = t >> 5;
    int mw = (NC == 128) ? (wid >> 1) : (wid >> 2);
    int nw = (NC == 128) ? (wid & 1) : (wid & 3);
    int wrow = mw * 32, wcol = nw * 64;
    int lr = lane >> 2, lc = lane & 3;
    int n0 = blockIdx.x * BM;

    float acc[2][8][4];
#pragma unroll
    for (int mt = 0; mt < 2; mt++)
#pragma unroll
        for (int nt = 0; nt < 8; nt++)
#pragma unroll
            for (int i = 0; i < 4; i++) acc[mt][nt][i] = 0.f;

    auto load_tiles = [&](int k0, int st) {
#pragma unroll
        for (int i = 0; i < BM / 64; i++) {
            int f = t + i * 256;
            int r = f >> 2, c4 = f & 3;
            int n = n0 + r;
            const float* src = A + (size_t)(n < NN ? n : 0) * K + k0 + c4 * 4;
            cp16(sptr(&As[st][r * SA + c4 * 4]), src, n < NN ? 16 : 0);
        }
#pragma unroll
        for (int i = 0; i < NC / 64; i++) {
            int f = t + i * 256;
            int r = f / (NC / 4), c4 = f % (NC / 4);
            cp16(sptr(&Bs[st][r * SB + c4 * 4]), Wt + (size_t)(k0 + r) * NC + c4 * 4, 16);
        }
    };

    load_tiles(0, 0);
    cp_commit();
    for (int c = 0; c < CH; c++) {
        int st = c & 1;
        if (c + 1 < CH) {
            load_tiles((c + 1) * KC, st ^ 1);
            cp_commit();
            cp_wait<1>();
        } else {
            cp_wait<0>();
        }
        __syncthreads();
#pragma unroll
        for (int ks = 0; ks < 2; ks++) {
            int kk = ks * 8;
            uint32_t a[2][4];
#pragma unroll
            for (int mt = 0; mt < 2; mt++) {
                int base = (wrow + mt * 16 + lr) * SA + kk + lc;
                if (CVTA) {
                    a[mt][0] = f2tf(As[st][base]);
                    a[mt][1] = f2tf(As[st][base + 8 * SA]);
                    a[mt][2] = f2tf(As[st][base + 4]);
                    a[mt][3] = f2tf(As[st][base + 8 * SA + 4]);
                } else {
                    a[mt][0] = __float_as_uint(As[st][base]);
                    a[mt][1] = __float_as_uint(As[st][base + 8 * SA]);
                    a[mt][2] = __float_as_uint(As[st][base + 4]);
                    a[mt][3] = __float_as_uint(As[st][base + 8 * SA + 4]);
                }
            }
            uint32_t b[8][2];
#pragma unroll
            for (int nt = 0; nt < 8; nt++) {
                int rb = (kk + lc) * SB + wcol + nt * 8 + lr;
                b[nt][0] = __float_as_uint(Bs[st][rb]);
                b[nt][1] = __float_as_uint(Bs[st][rb + 4 * SB]);
            }
#pragma unroll
            for (int mt = 0; mt < 2; mt++)
#pragma unroll
                for (int nt = 0; nt < 8; nt++)
                    mma_tf32(acc[mt][nt], a[mt], b[nt]);
        }
        __syncthreads();
    }

    // epilogue params per (nt, q) column
    float bsv[8][2], sc[8][2], sh[8][2];
#pragma unroll
    for (int nt = 0; nt < 8; nt++)
#pragma unroll
        for (int q = 0; q < 2; q++) {
            int col = wcol + nt * 8 + lc * 2 + q;
            bsv[nt][q] = bias[col];
            if (EPI == 0 || EPI == 1) {
                float s = bng[col] * rsqrtf(bnrv[col] + BN_EPS);
                sc[nt][q] = s;
                sh[nt][q] = bnb[col] - bnrm[col] * s;
            }
        }

    if (EPI == 1) {
        // compute v in-place in acc, reduce LN stats
#pragma unroll
        for (int mt = 0; mt < 2; mt++)
#pragma unroll
            for (int half = 0; half < 2; half++) {
                int row = wrow + mt * 16 + lr + half * 8;
                int n = n0 + row;
                float s = 0.f, sq = 0.f;
#pragma unroll
                for (int nt = 0; nt < 8; nt++)
#pragma unroll
                    for (int q = 0; q < 2; q++) {
                        int col = wcol + nt * 8 + lc * 2 + q;
                        float v = acc[mt][nt][half * 2 + q] + bsv[nt][q];
                        v = fmaxf(v * sc[nt][q] + sh[nt][q], 0.f);
                        if (n < NN) v += hres[(size_t)n * 512 + col];
                        acc[mt][nt][half * 2 + q] = v;
                        s += v;
                        sq += v * v;
                    }
                // quad reduce (lanes lr*4 + lc, lc in 0..3)
                s  += __shfl_xor_sync(0xffffffffu, s, 1);
                sq += __shfl_xor_sync(0xffffffffu, sq, 1);
                s  += __shfl_xor_sync(0xffffffffu, s, 2);
                sq += __shfl_xor_sync(0xffffffffu, sq, 2);
                if (lc == 0) {
                    red[(row * 2 + nw) * 2 + 0] = s;
                    red[(row * 2 + nw) * 2 + 1] = sq;
                }
            }
        __syncthreads();
#pragma unroll
        for (int mt = 0; mt < 2; mt++)
#pragma unroll
            for (int half = 0; half < 2; half++) {
                int row = wrow + mt * 16 + lr + half * 8;
                int n = n0 + row;
                if (n >= NN) continue;
                float s  = red[(row * 2 + 0) * 2 + 0] + red[(row * 2 + 1) * 2 + 0];
                float sq = red[(row * 2 + 0) * 2 + 1] + red[(row * 2 + 1) * 2 + 1];
                float mu = s * (1.f / 128.f);
                float var = sq * (1.f / 128.f) - mu * mu;
                float inv = rsqrtf(var + LN_EPS);
#pragma unroll
                for (int nt = 0; nt < 8; nt++)
#pragma unroll
                    for (int q = 0; q < 2; q++) {
                        int col = wcol + nt * 8 + lc * 2 + q;
                        float v = acc[mt][nt][half * 2 + q];
                        float o = (v - mu) * inv * lng[col] + lnb[col];
                        out[(size_t)n * OS + col] = o;
                    }
            }
        return;
    }

#pragma unroll
    for (int mt = 0; mt < 2; mt++)
#pragma unroll
        for (int half = 0; half < 2; half++) {
            int row = wrow + mt * 16 + lr + half * 8;
            int n = n0 + row;
            if (n >= NN) continue;
#pragma unroll
            for (int nt = 0; nt < 8; nt++)
#pragma unroll
                for (int q = 0; q < 2; q++) {
                    int col = wcol + nt * 8 + lc * 2 + q;
                    float v = acc[mt][nt][half * 2 + q] + bsv[nt][q];
                    if (EPI == 0) v = fmaxf(v * sc[nt][q] + sh[nt][q], 0.f);
                    if (EPI == 2) v = fmaxf(v, 0.f);
                    if (EPI == 0 || EPI == 2) v = __uint_as_float(f2tf(v));
                    out[(size_t)n * OS + col] = v;
                }
        }
}

// pooled sum with run-length pre-aggregation over sorted batch ids
__global__ void k_pool(const int* __restrict__ batch, const float* __restrict__ emb) {
    int c = blockIdx.x;
    int j = threadIdx.x;
    int n0 = c * 32;
    __shared__ int sb[32];
    if (j < 32) sb[j] = (n0 + j < NN) ? batch[n0 + j] : -1;
    __syncthreads();
    float acc = 0.f;
    int bcur = sb[0];
    for (int m = 0; m < 32; m++) {
        int b = sb[m];
        if (b < 0) break;
        if (b != bcur) {
            atomicAdd(&g_gsum[bcur * HH + j], acc);
            acc = 0.f;
            bcur = b;
        }
        acc += emb[(size_t)(n0 + m) * HH + j];
    }
    if (bcur >= 0) atomicAdd(&g_gsum[bcur * HH + j], acc);
    if (j == 0) {
        float cn = 0.f;
        int bc = sb[0];
        for (int m = 0; m < 32; m++) {
            int b = sb[m];
            if (b < 0) break;
            if (b != bc) { atomicAdd(&g_cnt[bc], cn); cn = 0.f; bc = b; }
            cn += 1.f;
        }
        if (bc >= 0) atomicAdd(&g_cnt[bc], cn);
    }
}

__global__ void k_finish(float* __restrict__ out_graph) {
    int i = blockIdx.x * blockDim.x + threadIdx.x;
    if (i >= BB * HH) return;
    out_graph[i] = g_gsum[i] / fmaxf(g_cnt[i >> 7], 1.f);
}

// ---------------- launcher ----------------------------------------------------
extern "C" void kernel_launch(void* const* d_in, const int* in_sizes, int n_in,
                              void* d_out, int out_size) {
    const float* x      = (const float*)d_in[0];
    const int*   ei     = (const int*)  d_in[1];
    const float* ea     = (const float*)d_in[2];
    const int*   batch  = (const int*)  d_in[3];
    const float* in_W   = (const float*)d_in[4];
    const float* in_b   = (const float*)d_in[5];
    const float* edge_W = (const float*)d_in[6];
    const float* edge_b = (const float*)d_in[7];
    const float* mlp_W1 = (const float*)d_in[8];
    const float* mlp_b1 = (const float*)d_in[9];
    const float* bn1_g  = (const float*)d_in[10];
    const float* bn1_b  = (const float*)d_in[11];
    const float* bn1_rm = (const float*)d_in[12];
    const float* bn1_rv = (const float*)d_in[13];
    const float* mlp_W2 = (const float*)d_in[14];
    const float* mlp_b2 = (const float*)d_in[15];
    const float* bn2_g  = (const float*)d_in[16];
    const float* bn2_b  = (const float*)d_in[17];
    const float* bn2_rm = (const float*)d_in[18];
    const float* bn2_rv = (const float*)d_in[19];
    const float* eps    = (const float*)d_in[20];
    const float* ln_g   = (const float*)d_in[21];
    const float* ln_b   = (const float*)d_in[22];
    const float* out_W1 = (const float*)d_in[23];
    const float* out_b1 = (const float*)d_in[24];
    const float* out_W2 = (const float*)d_in[25];
    const float* out_b2 = (const float*)d_in[26];

    float* node_emb  = (float*)d_out;                       // [N, H]
    float* graph_emb = (float*)d_out + (size_t)NN * HH;     // [B, H]

    float* g_hcat_p; cudaGetSymbolAddress((void**)&g_hcat_p, g_hcat);
    float* g_agg_p;  cudaGetSymbolAddress((void**)&g_agg_p,  g_agg);
    float* g_z1_p;   cudaGetSymbolAddress((void**)&g_z1_p,   g_z1);
    float* g_wtf_p;  cudaGetSymbolAddress((void**)&g_wtf_p,  g_wtf);

    const int NT = 256;
    k_init<<<(NN + NT - 1) / NT, NT>>>();
    k_wcvt<<<(WTOT + NT - 1) / NT, NT>>>(mlp_W1, mlp_W2, out_W1, out_W2);
    k_input<<<(NN * HH + NT - 1) / NT, NT>>>(x, in_W, in_b);

    // CSR build (edge list shared across layers)
    k_count<<<(EE + NT - 1) / NT, NT>>>(ei);
    k_scan1<<<(NN + 1023) / 1024, 256>>>();
    k_scan2<<<1, 128>>>((NN + 1023) / 1024);
    k_scan3<<<(NN + NT - 1) / NT, NT>>>();
    k_place<<<(EE + NT - 1) / NT, NT>>>(ei, ea);

    const int grid128 = (NN + 127) / 128;   // NC=128 configs (BM=128)
    const int grid64  = (NN + 63) / 64;     // NC=256 configs (BM=64)
    for (int l = 0; l < LL; l++) {
        k_gather<<<(NN * 32 + NT - 1) / NT, NT>>>(edge_W, edge_b, eps, l);
        // mlp1: agg[N,128](tf32) @ W1 -> z1[N,256] tf32, bn1+relu
        k_gemm<128, 256, 0, 0><<<grid64, 256>>>(
            g_agg_p, g_wtf_p + W1TF + (size_t)l * 128 * 256, mlp_b1 + l * 256,
            bn1_g + l * 256, bn1_b + l * 256, bn1_rm + l * 256, bn1_rv + l * 256,
            nullptr, nullptr, nullptr, g_z1_p);
        // mlp2: z1[N,256](tf32) @ W2 -> bn2+relu+residual -> fused LN -> hcat slot l+1
        k_gemm<256, 128, 1, 0><<<grid128, 256>>>(
            g_z1_p, g_wtf_p + W2TF + (size_t)l * 256 * 128, mlp_b2 + l * 128,
            bn2_g + l * 128, bn2_b + l * 128, bn2_rm + l * 128, bn2_rv + l * 128,
            g_hcat_p + l * HH, ln_g + l * 128, ln_b + l * 128,
            g_hcat_p + (l + 1) * HH);
    }
    // out1: hcat[N,512](fp32, CVTA) @ W1 -> relu -> g_z1[N,128] tf32
    k_gemm<512, 128, 2, 1><<<grid128, 256>>>(
        g_hcat_p, g_wtf_p + O1TF, out_b1, nullptr, nullptr, nullptr, nullptr,
        nullptr, nullptr, nullptr, g_z1_p);
    // out2: g_z1[N,128](tf32) @ W2 -> node_emb fp32
    k_gemm<128, 128, 3, 0><<<grid128, 256>>>(
        g_z1_p, g_wtf_p + O2TF, out_b2, nullptr, nullptr, nullptr, nullptr,
        nullptr, nullptr, nullptr, node_emb);

    k_pool<<<(NN + 31) / 32, 128>>>(batch, node_emb);
    k_finish<<<(BB * HH + NT - 1) / NT, NT>>>(graph_emb);
}